// round 5
// baseline (speedup 1.0000x reference)
#include <cuda_runtime.h>

#define N_NODES 100000
#define N_EDGES 1600000
#define IN_SIZE 512
#define HID 256
#define OUTD 40
#define KSTEPS 10
#define ALPHA 0.1f

// ---------------- scratch (device globals; no allocation allowed) ----------
__device__ float g_h1[(size_t)N_NODES * HID];     // MLP hidden activations
__device__ float g_h0[(size_t)N_NODES * OUTD];    // h0 (teleport term)
__device__ float g_hsA[(size_t)N_NODES * OUTD];   // ping-pong pre-scaled h
__device__ float g_hsB[(size_t)N_NODES * OUTD];
__device__ int   g_deg_out[N_NODES];
__device__ int   g_deg_in[N_NODES];
__device__ int   g_cursor[N_NODES];
__device__ float g_norm_src[N_NODES];
__device__ float g_norm_dst[N_NODES];
__device__ int   g_rowptr[N_NODES + 1];
__device__ int   g_col[N_EDGES];                  // CSR by dst: src ids (int32)

// ---------------- preprocessing ----------------
__global__ void zero_kernel() {
    int i = blockIdx.x * blockDim.x + threadIdx.x;
    if (i < N_NODES) {
        g_deg_out[i] = 0;
        g_deg_in[i]  = 0;
        g_cursor[i]  = 0;
    }
}

// NOTE: edge indices arrive as int32 (JAX x64-disabled downcasts the reference's
// int64 request; harness dtype table only carries int32). Reading them as
// long long was the R4 illegal-access root cause.
__global__ void degree_kernel(const int* __restrict__ src,
                              const int* __restrict__ dst) {
    int e = blockIdx.x * blockDim.x + threadIdx.x;
    if (e < N_EDGES) {
        atomicAdd(&g_deg_out[src[e]], 1);
        atomicAdd(&g_deg_in[dst[e]], 1);
    }
}

__global__ void norm_kernel() {
    int n = blockIdx.x * blockDim.x + threadIdx.x;
    if (n < N_NODES) {
        int dOut = g_deg_out[n]; if (dOut < 1) dOut = 1;
        int dIn  = g_deg_in[n];  if (dIn  < 1) dIn  = 1;
        g_norm_src[n] = rsqrtf((float)dOut);
        g_norm_dst[n] = rsqrtf((float)dIn);
    }
}

// single-block exclusive scan of g_deg_in -> g_rowptr (warp-shuffle, 3 bars/tile)
__global__ void scan_kernel() {
    __shared__ int warp_sums[32];
    __shared__ int carry_sh;
    int tid  = threadIdx.x;
    int lane = tid & 31;
    int wid  = tid >> 5;
    if (tid == 0) carry_sh = 0;
    __syncthreads();
    for (int base = 0; base < N_NODES; base += 1024) {
        int i = base + tid;
        int v = (i < N_NODES) ? g_deg_in[i] : 0;
        int x = v;
        #pragma unroll
        for (int off = 1; off < 32; off <<= 1) {
            int t = __shfl_up_sync(0xffffffffu, x, off);
            if (lane >= off) x += t;
        }
        if (lane == 31) warp_sums[wid] = x;
        __syncthreads();
        if (wid == 0) {
            int ws = warp_sums[lane];
            #pragma unroll
            for (int off = 1; off < 32; off <<= 1) {
                int t = __shfl_up_sync(0xffffffffu, ws, off);
                if (lane >= off) ws += t;
            }
            warp_sums[lane] = ws;   // inclusive scan of warp sums
        }
        __syncthreads();
        int warp_base = (wid > 0) ? warp_sums[wid - 1] : 0;
        int incl = warp_base + x;
        if (i < N_NODES) g_rowptr[i] = carry_sh + incl - v;  // exclusive
        __syncthreads();
        if (tid == 1023) carry_sh += incl;  // tile total
        __syncthreads();
    }
    if (tid == 0) g_rowptr[N_NODES] = carry_sh;
}

__global__ void scatter_kernel(const int* __restrict__ src,
                               const int* __restrict__ dst) {
    int e = blockIdx.x * blockDim.x + threadIdx.x;
    if (e < N_EDGES) {
        int d = dst[e];
        int pos = atomicAdd(&g_cursor[d], 1);
        g_col[g_rowptr[d] + pos] = src[e];
    }
}

// ---------------- MLP layer 1: h1 = relu(X @ W1 + b1) ----------------
// classic SGEMM: BM=128, BN=128, BK=8, 256 threads, 8x8 per thread
__global__ void __launch_bounds__(256, 2)
mlp1_kernel(const float* __restrict__ X, const float* __restrict__ W1,
            const float* __restrict__ b1) {
    __shared__ float As[8][128];
    __shared__ float Bs[8][128];
    const int K = IN_SIZE;       // 512
    const int N = HID;           // 256
    const int M = N_NODES;
    int tid = threadIdx.x;
    int bcol = blockIdx.x;       // 0..1
    int brow = blockIdx.y;       // 0..781

    int a_row = tid >> 1;            // 0..127
    int a_col = (tid & 1) * 4;       // 0 or 4
    int b_row = tid >> 5;            // 0..7
    int b_col = (tid & 31) * 4;      // 0..124
    int tx = tid & 15, ty = tid >> 4;
    int grow = brow * 128;

    float acc[8][8];
    #pragma unroll
    for (int i = 0; i < 8; i++)
        #pragma unroll
        for (int j = 0; j < 8; j++) acc[i][j] = 0.f;

    for (int k0 = 0; k0 < K; k0 += 8) {
        int row = grow + a_row;
        float4 av = make_float4(0.f, 0.f, 0.f, 0.f);
        if (row < M)
            av = *(const float4*)(X + (long)row * K + k0 + a_col);
        As[a_col + 0][a_row] = av.x;
        As[a_col + 1][a_row] = av.y;
        As[a_col + 2][a_row] = av.z;
        As[a_col + 3][a_row] = av.w;
        float4 bv = *(const float4*)(W1 + (long)(k0 + b_row) * N + bcol * 128 + b_col);
        *(float4*)(&Bs[b_row][b_col]) = bv;
        __syncthreads();
        #pragma unroll
        for (int k = 0; k < 8; k++) {
            float ra[8], rb[8];
            #pragma unroll
            for (int i = 0; i < 8; i++) ra[i] = As[k][ty * 8 + i];
            #pragma unroll
            for (int j = 0; j < 8; j++) rb[j] = Bs[k][tx * 8 + j];
            #pragma unroll
            for (int i = 0; i < 8; i++)
                #pragma unroll
                for (int j = 0; j < 8; j++) acc[i][j] += ra[i] * rb[j];
        }
        __syncthreads();
    }
    #pragma unroll
    for (int i = 0; i < 8; i++) {
        int row = grow + ty * 8 + i;
        if (row >= M) continue;
        #pragma unroll
        for (int j = 0; j < 8; j++) {
            int col = bcol * 128 + tx * 8 + j;
            float v = acc[i][j] + b1[col];
            g_h1[(long)row * HID + col] = fmaxf(v, 0.f);
        }
    }
}

// ---------------- MLP layer 2 + init: h0 = h1 @ W2 + b2 ; hsA = h0*norm_src
// block: 320 threads = 32 rows x 10 col-groups (4 cols each)
__global__ void __launch_bounds__(320)
mlp2_kernel(const float* __restrict__ W2, const float* __restrict__ b2) {
    __shared__ float sh[32 * 264];   // 32 rows x 256, padded stride 264
    int tid = threadIdx.x;
    int brow = blockIdx.x * 32;
    for (int i = tid; i < 2048; i += 320) {
        int r = i >> 6, c4 = i & 63;
        float4 v = *(const float4*)(g_h1 + (long)(brow + r) * HID + c4 * 4);
        sh[r * 264 + c4 * 4 + 0] = v.x;
        sh[r * 264 + c4 * 4 + 1] = v.y;
        sh[r * 264 + c4 * 4 + 2] = v.z;
        sh[r * 264 + c4 * 4 + 3] = v.w;
    }
    __syncthreads();
    int r  = tid / 10;   // 0..31
    int cg = tid % 10;   // 0..9
    float4 acc = make_float4(0.f, 0.f, 0.f, 0.f);
    #pragma unroll 4
    for (int k = 0; k < HID; k++) {
        float a = sh[r * 264 + k];
        float4 w = __ldg((const float4*)(W2 + (long)k * OUTD + cg * 4));
        acc.x += a * w.x;
        acc.y += a * w.y;
        acc.z += a * w.z;
        acc.w += a * w.w;
    }
    int n = brow + r;
    float ns = g_norm_src[n];
    float4 bb = __ldg((const float4*)(b2 + cg * 4));
    float4 h0v;
    h0v.x = acc.x + bb.x;
    h0v.y = acc.y + bb.y;
    h0v.z = acc.z + bb.z;
    h0v.w = acc.w + bb.w;
    *(float4*)(g_h0 + (long)n * OUTD + cg * 4) = h0v;
    float4 hsv;
    hsv.x = h0v.x * ns; hsv.y = h0v.y * ns; hsv.z = h0v.z * ns; hsv.w = h0v.w * ns;
    *(float4*)(g_hsA + (long)n * OUTD + cg * 4) = hsv;
}

// ---------------- propagation step: warp-per-node CSR gather --------------
// h_new = (1-a) * norm_dst * sum_{e: dst=n} hs_in[src_e]  +  a * h0
// out <- h_new ; hs_out <- h_new * norm_src
// Row = 40 floats = 10 float4: lanes 0..9 each own one float4 column slice.
// Ping-pong buffers selected in device code (no host symbol APIs under capture).
__global__ void __launch_bounds__(256)
prop_kernel(int odd, float* __restrict__ out) {
    const float* hs_in  = odd ? g_hsB : g_hsA;
    float*       hs_out = odd ? g_hsA : g_hsB;
    int gwarp = (blockIdx.x * blockDim.x + threadIdx.x) >> 5;
    int lane = threadIdx.x & 31;
    if (gwarp >= N_NODES) return;
    int rs = g_rowptr[gwarp];
    int re = g_rowptr[gwarp + 1];
    float4 acc = make_float4(0.f, 0.f, 0.f, 0.f);
    bool active = lane < 10;
    for (int e = rs; e < re; ++e) {
        int s = __ldg(&g_col[e]);
        if (active) {
            float4 v = __ldg((const float4*)(hs_in + (long)s * OUTD) + lane);
            acc.x += v.x; acc.y += v.y; acc.z += v.z; acc.w += v.w;
        }
    }
    if (active) {
        float nd = g_norm_dst[gwarp];
        float ns = g_norm_src[gwarp];
        const float oma = 1.0f - ALPHA;
        long base4 = (long)gwarp * 10 + lane;   // float4 index
        float4 h0v = ((const float4*)g_h0)[base4];
        float4 v;
        v.x = oma * acc.x * nd + ALPHA * h0v.x;
        v.y = oma * acc.y * nd + ALPHA * h0v.y;
        v.z = oma * acc.z * nd + ALPHA * h0v.z;
        v.w = oma * acc.w * nd + ALPHA * h0v.w;
        ((float4*)out)[base4] = v;
        float4 sv;
        sv.x = v.x * ns; sv.y = v.y * ns; sv.z = v.z * ns; sv.w = v.w * ns;
        ((float4*)hs_out)[base4] = sv;
    }
}

// ---------------- launch --------------------------------------------------
extern "C" void kernel_launch(void* const* d_in, const int* in_sizes, int n_in,
                              void* d_out, int out_size) {
    const float* X   = (const float*)d_in[0];
    const int*   src = (const int*)d_in[1];
    const int*   dst = (const int*)d_in[2];
    const float* W1  = (const float*)d_in[3];
    const float* b1  = (const float*)d_in[4];
    const float* W2  = (const float*)d_in[5];
    const float* b2  = (const float*)d_in[6];
    float* out = (float*)d_out;

    // preprocessing: degrees, norms, CSR(dst)
    zero_kernel<<<(N_NODES + 255) / 256, 256>>>();
    degree_kernel<<<(N_EDGES + 255) / 256, 256>>>(src, dst);
    norm_kernel<<<(N_NODES + 255) / 256, 256>>>();
    scan_kernel<<<1, 1024>>>();
    scatter_kernel<<<(N_EDGES + 255) / 256, 256>>>(src, dst);

    // MLP encoder
    {
        dim3 grid(HID / 128, (N_NODES + 127) / 128);
        mlp1_kernel<<<grid, 256>>>(X, W1, b1);
    }
    mlp2_kernel<<<N_NODES / 32, 320>>>(W2, b2);

    // 10 APPNP steps, ping-pong hs buffers; each writes d_out (last one wins)
    int prop_blocks = (N_NODES * 32 + 255) / 256;
    for (int k = 0; k < KSTEPS; ++k) {
        prop_kernel<<<prop_blocks, 256>>>(k & 1, out);
    }
}

// round 11
// speedup vs baseline: 1.4590x; 1.4590x over previous
#include <cuda_runtime.h>
#include <cstdint>

#define N_NODES 100000
#define N_EDGES 1600000
#define IN_SIZE 512
#define HID 256
#define OUTD 40
#define KSTEPS 10
#define ALPHA 0.1f
#define NB_SCAN 98   // ceil(100000/1024)

// ---------------- scratch (device globals; no allocation allowed) ----------
__device__ float g_h1[(size_t)N_NODES * HID];
__device__ float g_h0[(size_t)N_NODES * OUTD];
__device__ float g_hsA[(size_t)N_NODES * OUTD];
__device__ float g_hsB[(size_t)N_NODES * OUTD];
__device__ int   g_deg_out[N_NODES];
__device__ int   g_deg_in[N_NODES];
__device__ int   g_cursor[N_NODES];
__device__ float g_norm_src[N_NODES];
__device__ float g_norm_dst[N_NODES];
__device__ int   g_rowptr[N_NODES + 1];
__device__ int   g_col[N_EDGES];
__device__ int   g_bsum[128];
__device__ int   g_boff[128];

// ---------------- preprocessing ----------------
__global__ void zero_kernel() {
    int i = blockIdx.x * blockDim.x + threadIdx.x;
    if (i < N_NODES) {
        g_deg_out[i] = 0;
        g_deg_in[i]  = 0;
        g_cursor[i]  = 0;
    }
}

__global__ void degree_kernel(const int* __restrict__ src,
                              const int* __restrict__ dst) {
    int e = blockIdx.x * blockDim.x + threadIdx.x;
    if (e < N_EDGES) {
        atomicAdd(&g_deg_out[src[e]], 1);
        atomicAdd(&g_deg_in[dst[e]], 1);
    }
}

__global__ void norm_kernel() {
    int n = blockIdx.x * blockDim.x + threadIdx.x;
    if (n < N_NODES) {
        int dOut = g_deg_out[n]; if (dOut < 1) dOut = 1;
        int dIn  = g_deg_in[n];  if (dIn  < 1) dIn  = 1;
        g_norm_src[n] = rsqrtf((float)dOut);
        g_norm_dst[n] = rsqrtf((float)dIn);
    }
}

__device__ __forceinline__ int warp_incl_scan(int x, int lane) {
    #pragma unroll
    for (int off = 1; off < 32; off <<= 1) {
        int t = __shfl_up_sync(0xffffffffu, x, off);
        if (lane >= off) x += t;
    }
    return x;
}

// K1: per-block (1024) exclusive scan of deg_in -> rowptr (local), block totals
__global__ void scan_block_kernel() {
    __shared__ int wsums[32];
    int tid = threadIdx.x, lane = tid & 31, wid = tid >> 5;
    int i = blockIdx.x * 1024 + tid;
    int v = (i < N_NODES) ? g_deg_in[i] : 0;
    int x = warp_incl_scan(v, lane);
    if (lane == 31) wsums[wid] = x;
    __syncthreads();
    if (wid == 0) wsums[lane] = warp_incl_scan(wsums[lane], lane);
    __syncthreads();
    int incl = ((wid > 0) ? wsums[wid - 1] : 0) + x;
    if (i < N_NODES) g_rowptr[i] = incl - v;      // block-local exclusive
    if (tid == 1023) g_bsum[blockIdx.x] = incl;   // block total
}

// K2: one block (128 thr) exclusive scan of the 98 block totals
__global__ void scan_tops_kernel() {
    __shared__ int wsum[4], woff[4];
    int tid = threadIdx.x, lane = tid & 31, wid = tid >> 5;
    int v = (tid < NB_SCAN) ? g_bsum[tid] : 0;
    int x = warp_incl_scan(v, lane);
    if (lane == 31) wsum[wid] = x;
    __syncthreads();
    if (tid == 0) {
        int r = 0;
        #pragma unroll
        for (int w = 0; w < 4; w++) { woff[w] = r; r += wsum[w]; }
        g_rowptr[N_NODES] = r;   // total edge count
    }
    __syncthreads();
    if (tid < NB_SCAN) g_boff[tid] = woff[wid] + x - v;  // exclusive
}

// K3: add block offsets
__global__ void scan_add_kernel() {
    int i = blockIdx.x * 256 + threadIdx.x;
    if (i < N_NODES) g_rowptr[i] += g_boff[i >> 10];
}

__global__ void scatter_kernel(const int* __restrict__ src,
                               const int* __restrict__ dst) {
    int e = blockIdx.x * blockDim.x + threadIdx.x;
    if (e < N_EDGES) {
        int d = dst[e];
        int pos = atomicAdd(&g_cursor[d], 1);
        g_col[g_rowptr[d] + pos] = src[e];
    }
}

// ---------------- MLP layer 1 (TF32 tensor cores) ----------------
// h1 = relu(X @ W1 + b1).  BM=128, BN=128, BK=16, 256 thr (8 warps = 4Mx2N),
// warp tile 32x64, mma.sync m16n8k8 tf32, fp32 accum. Double-buffered smem,
// tf32 conversion (cvt.rna) done once at staging. Stride 136 words -> all
// fragment LDS and staging STS are bank-conflict-free.
__device__ __forceinline__ uint32_t f2tf32(float f) {
    uint32_t u;
    asm("cvt.rna.tf32.f32 %0, %1;" : "=r"(u) : "f"(f));
    return u;
}

__device__ __forceinline__ void mma_tf32(float* c, const uint32_t* a,
                                         uint32_t b0, uint32_t b1) {
    asm volatile(
        "mma.sync.aligned.m16n8k8.row.col.f32.tf32.tf32.f32 "
        "{%0,%1,%2,%3}, {%4,%5,%6,%7}, {%8,%9}, {%0,%1,%2,%3};"
        : "+f"(c[0]), "+f"(c[1]), "+f"(c[2]), "+f"(c[3])
        : "r"(a[0]), "r"(a[1]), "r"(a[2]), "r"(a[3]), "r"(b0), "r"(b1));
}

#define MLP1_BK 16
#define MLP1_STR 136   // 128 + 8 pad (words)

__global__ void __launch_bounds__(256)
mlp1_mma_kernel(const float* __restrict__ X, const float* __restrict__ W1,
                const float* __restrict__ b1) {
    __shared__ __align__(16) float As[2][MLP1_BK][MLP1_STR];  // [k][m], tf32
    __shared__ __align__(16) float Bs[2][MLP1_BK][MLP1_STR];  // [k][n], tf32
    const int K = IN_SIZE, N = HID, M = N_NODES;
    int tid = threadIdx.x;
    int wid = tid >> 5, lane = tid & 31;
    int g = lane >> 2, tig = lane & 3;
    int warp_m = wid >> 1, warp_n = wid & 1;
    int m0 = blockIdx.y * 128;
    int n0 = blockIdx.x * 128;
    int m0w = warp_m * 32, n0w = warp_n * 64;

    float acc[2][8][4];
    #pragma unroll
    for (int mt = 0; mt < 2; mt++)
        #pragma unroll
        for (int j = 0; j < 8; j++)
            #pragma unroll
            for (int c = 0; c < 4; c++) acc[mt][j][c] = 0.f;

    // staging index maps
    int am  = tid & 127;   // m within tile (A)
    int akq = tid >> 7;    // 0/1 -> k-quads {akq, akq+2}
    const int nkt = K / MLP1_BK;   // 32

    // prologue: stage tile 0 into buffer 0
    {
        int row = m0 + am;
        #pragma unroll
        for (int q = 0; q < 2; q++) {
            int kq = akq + q * 2;
            float4 f = make_float4(0.f, 0.f, 0.f, 0.f);
            if (row < M) f = *(const float4*)(X + (long)row * K + kq * 4);
            As[0][kq * 4 + 0][am] = __uint_as_float(f2tf32(f.x));
            As[0][kq * 4 + 1][am] = __uint_as_float(f2tf32(f.y));
            As[0][kq * 4 + 2][am] = __uint_as_float(f2tf32(f.z));
            As[0][kq * 4 + 3][am] = __uint_as_float(f2tf32(f.w));
        }
        #pragma unroll
        for (int q = 0; q < 2; q++) {
            int idx = tid + q * 256;
            int kr = idx >> 5, c = idx & 31;
            float4 f = *(const float4*)(W1 + (long)kr * N + n0 + c * 4);
            float4 t;
            t.x = __uint_as_float(f2tf32(f.x));
            t.y = __uint_as_float(f2tf32(f.y));
            t.z = __uint_as_float(f2tf32(f.z));
            t.w = __uint_as_float(f2tf32(f.w));
            *(float4*)&Bs[0][kr][c * 4] = t;
        }
    }
    __syncthreads();

    for (int kt = 0; kt < nkt; kt++) {
        int cur = kt & 1, nxt = cur ^ 1;
        // prefetch next tile into regs
        float4 ar[2], br[2];
        bool has_next = (kt + 1 < nkt);
        if (has_next) {
            int kbase = (kt + 1) * MLP1_BK;
            int row = m0 + am;
            #pragma unroll
            for (int q = 0; q < 2; q++) {
                int kq = akq + q * 2;
                ar[q] = make_float4(0.f, 0.f, 0.f, 0.f);
                if (row < M)
                    ar[q] = *(const float4*)(X + (long)row * K + kbase + kq * 4);
            }
            #pragma unroll
            for (int q = 0; q < 2; q++) {
                int idx = tid + q * 256;
                int kr = idx >> 5, c = idx & 31;
                br[q] = *(const float4*)(W1 + (long)(kbase + kr) * N + n0 + c * 4);
            }
        }
        // compute current tile: 2 k-steps of 8
        #pragma unroll
        for (int ks = 0; ks < 2; ks++) {
            int kb = ks * 8;
            uint32_t a[2][4];
            #pragma unroll
            for (int mt = 0; mt < 2; mt++) {
                int mm = m0w + mt * 16 + g;
                a[mt][0] = __float_as_uint(As[cur][kb + tig][mm]);
                a[mt][1] = __float_as_uint(As[cur][kb + tig][mm + 8]);
                a[mt][2] = __float_as_uint(As[cur][kb + tig + 4][mm]);
                a[mt][3] = __float_as_uint(As[cur][kb + tig + 4][mm + 8]);
            }
            #pragma unroll
            for (int j = 0; j < 8; j++) {
                int nn = n0w + j * 8 + g;
                uint32_t b0 = __float_as_uint(Bs[cur][kb + tig][nn]);
                uint32_t b1r = __float_as_uint(Bs[cur][kb + tig + 4][nn]);
                mma_tf32(acc[0][j], a[0], b0, b1r);
                mma_tf32(acc[1][j], a[1], b0, b1r);
            }
        }
        // stage prefetched tile
        if (has_next) {
            #pragma unroll
            for (int q = 0; q < 2; q++) {
                int kq = akq + q * 2;
                As[nxt][kq * 4 + 0][am] = __uint_as_float(f2tf32(ar[q].x));
                As[nxt][kq * 4 + 1][am] = __uint_as_float(f2tf32(ar[q].y));
                As[nxt][kq * 4 + 2][am] = __uint_as_float(f2tf32(ar[q].z));
                As[nxt][kq * 4 + 3][am] = __uint_as_float(f2tf32(ar[q].w));
            }
            #pragma unroll
            for (int q = 0; q < 2; q++) {
                int idx = tid + q * 256;
                int kr = idx >> 5, c = idx & 31;
                float4 t;
                t.x = __uint_as_float(f2tf32(br[q].x));
                t.y = __uint_as_float(f2tf32(br[q].y));
                t.z = __uint_as_float(f2tf32(br[q].z));
                t.w = __uint_as_float(f2tf32(br[q].w));
                *(float4*)&Bs[nxt][kr][c * 4] = t;
            }
        }
        __syncthreads();
    }

    // epilogue: bias + relu + store
    #pragma unroll
    for (int mt = 0; mt < 2; mt++) {
        #pragma unroll
        for (int j = 0; j < 8; j++) {
            int col0 = n0 + n0w + j * 8 + tig * 2;
            float bb0 = __ldg(b1 + col0);
            float bb1 = __ldg(b1 + col0 + 1);
            int r0 = m0 + m0w + mt * 16 + g;
            int r1 = r0 + 8;
            if (r0 < M) {
                g_h1[(long)r0 * HID + col0]     = fmaxf(acc[mt][j][0] + bb0, 0.f);
                g_h1[(long)r0 * HID + col0 + 1] = fmaxf(acc[mt][j][1] + bb1, 0.f);
            }
            if (r1 < M) {
                g_h1[(long)r1 * HID + col0]     = fmaxf(acc[mt][j][2] + bb0, 0.f);
                g_h1[(long)r1 * HID + col0 + 1] = fmaxf(acc[mt][j][3] + bb1, 0.f);
            }
        }
    }
}

// ---------------- MLP layer 2 + init ----------------
__global__ void __launch_bounds__(320)
mlp2_kernel(const float* __restrict__ W2, const float* __restrict__ b2) {
    __shared__ float sh[32 * 264];
    int tid = threadIdx.x;
    int brow = blockIdx.x * 32;
    for (int i = tid; i < 2048; i += 320) {
        int r = i >> 6, c4 = i & 63;
        float4 v = *(const float4*)(g_h1 + (long)(brow + r) * HID + c4 * 4);
        sh[r * 264 + c4 * 4 + 0] = v.x;
        sh[r * 264 + c4 * 4 + 1] = v.y;
        sh[r * 264 + c4 * 4 + 2] = v.z;
        sh[r * 264 + c4 * 4 + 3] = v.w;
    }
    __syncthreads();
    int r  = tid / 10;
    int cg = tid % 10;
    float4 acc = make_float4(0.f, 0.f, 0.f, 0.f);
    #pragma unroll 4
    for (int k = 0; k < HID; k++) {
        float a = sh[r * 264 + k];
        float4 w = __ldg((const float4*)(W2 + (long)k * OUTD + cg * 4));
        acc.x += a * w.x;
        acc.y += a * w.y;
        acc.z += a * w.z;
        acc.w += a * w.w;
    }
    int n = brow + r;
    float ns = g_norm_src[n];
    float4 bb = __ldg((const float4*)(b2 + cg * 4));
    float4 h0v;
    h0v.x = acc.x + bb.x;
    h0v.y = acc.y + bb.y;
    h0v.z = acc.z + bb.z;
    h0v.w = acc.w + bb.w;
    *(float4*)(g_h0 + (long)n * OUTD + cg * 4) = h0v;
    float4 hsv;
    hsv.x = h0v.x * ns; hsv.y = h0v.y * ns; hsv.z = h0v.z * ns; hsv.w = h0v.w * ns;
    *(float4*)(g_hsA + (long)n * OUTD + cg * 4) = hsv;
}

// ---------------- propagation step ----------------
__global__ void __launch_bounds__(256)
prop_kernel(int odd, int last, float* __restrict__ out) {
    const float* hs_in  = odd ? g_hsB : g_hsA;
    float*       hs_out = odd ? g_hsA : g_hsB;
    int gwarp = (blockIdx.x * blockDim.x + threadIdx.x) >> 5;
    int lane = threadIdx.x & 31;
    if (gwarp >= N_NODES) return;
    int rs = g_rowptr[gwarp];
    int re = g_rowptr[gwarp + 1];
    float4 acc = make_float4(0.f, 0.f, 0.f, 0.f);
    bool active = lane < 10;
    for (int e = rs; e < re; ++e) {
        int s = __ldg(&g_col[e]);
        if (active) {
            float4 v = __ldg((const float4*)(hs_in + (long)s * OUTD) + lane);
            acc.x += v.x; acc.y += v.y; acc.z += v.z; acc.w += v.w;
        }
    }
    if (active) {
        float nd = g_norm_dst[gwarp];
        float ns = g_norm_src[gwarp];
        const float oma = 1.0f - ALPHA;
        long base4 = (long)gwarp * 10 + lane;
        float4 h0v = ((const float4*)g_h0)[base4];
        float4 v;
        v.x = oma * acc.x * nd + ALPHA * h0v.x;
        v.y = oma * acc.y * nd + ALPHA * h0v.y;
        v.z = oma * acc.z * nd + ALPHA * h0v.z;
        v.w = oma * acc.w * nd + ALPHA * h0v.w;
        if (last) {
            ((float4*)out)[base4] = v;
        } else {
            float4 sv;
            sv.x = v.x * ns; sv.y = v.y * ns; sv.z = v.z * ns; sv.w = v.w * ns;
            ((float4*)hs_out)[base4] = sv;
        }
    }
}

// ---------------- launch --------------------------------------------------
extern "C" void kernel_launch(void* const* d_in, const int* in_sizes, int n_in,
                              void* d_out, int out_size) {
    const float* X   = (const float*)d_in[0];
    const int*   src = (const int*)d_in[1];
    const int*   dst = (const int*)d_in[2];
    const float* W1  = (const float*)d_in[3];
    const float* b1  = (const float*)d_in[4];
    const float* W2  = (const float*)d_in[5];
    const float* b2  = (const float*)d_in[6];
    float* out = (float*)d_out;

    // preprocessing: degrees, norms, CSR(dst)
    zero_kernel<<<(N_NODES + 255) / 256, 256>>>();
    degree_kernel<<<(N_EDGES + 255) / 256, 256>>>(src, dst);
    norm_kernel<<<(N_NODES + 255) / 256, 256>>>();
    scan_block_kernel<<<NB_SCAN, 1024>>>();
    scan_tops_kernel<<<1, 128>>>();
    scan_add_kernel<<<(N_NODES + 255) / 256, 256>>>();
    scatter_kernel<<<(N_EDGES + 255) / 256, 256>>>(src, dst);

    // MLP encoder
    {
        dim3 grid(HID / 128, (N_NODES + 127) / 128);
        mlp1_mma_kernel<<<grid, 256>>>(X, W1, b1);
    }
    mlp2_kernel<<<N_NODES / 32, 320>>>(W2, b2);

    // 10 APPNP steps, ping-pong hs buffers; last writes d_out only
    int prop_blocks = (N_NODES * 32 + 255) / 256;
    for (int k = 0; k < KSTEPS; ++k) {
        prop_kernel<<<prop_blocks, 256>>>(k & 1, k == KSTEPS - 1, out);
    }
}